// round 5
// baseline (speedup 1.0000x reference)
#include <cuda_runtime.h>
#include <cstdint>

#define H       128
#define NNODES  4096
#define DEG     32
#define NPREP   17
#define NMAIN   128
#define NGRID   (NPREP + NMAIN)
#define FULLM   0xFFFFFFFFu
#define XPQ     260
#define SMEM_WORDS 26656
#define SMEM_BYTES (SMEM_WORDS*4)

// ---------------- device scratch ----------------
__device__ float g_Qtab[32*H];
__device__ float g_KtabT[H*32];     // transposed: [t][j]
__device__ float g_RtabT[H*32];     // transposed: [t][j]
__device__ float g_Vtab[32*H];
__device__ float g_U1[16*H];
__device__ float g_U2[16*H];
__device__ float g_U3[4*H];
__device__ float g_thr[32];
__device__ float g_nscal[NNODES];
__device__ int   g_row[NNODES];
__device__ int   g_arrive;          // zero-init
__device__ int   g_done;            // zero-init

__device__ __forceinline__ unsigned fkey(float f) {
    unsigned u = __float_as_uint(f);
    return (u & 0x80000000u) ? ~u : (u | 0x80000000u);
}

__global__ __launch_bounds__(1024, 1) void k_all(
    const float* __restrict__ scalars,     const int* __restrict__ node_states,
    const int*   __restrict__ edge_states,
    const float* __restrict__ emb_virtual, const float* __restrict__ emb_reciever,
    const float* __restrict__ emb_edge,    const float* __restrict__ emb_static,
    const float* __restrict__ w_q,  const float* __restrict__ w_k,
    const float* __restrict__ w_v,  const float* __restrict__ w_ek,
    const float* __restrict__ w_ev, const float* __restrict__ w_comb,
    const float* __restrict__ ln_q_g, const float* __restrict__ ln_q_b,
    const float* __restrict__ ln_k_g, const float* __restrict__ ln_k_b,
    const float* __restrict__ tg_w1, const float* __restrict__ tg_b1,
    const float* __restrict__ tg_w2, const float* __restrict__ tg_b2,
    float* __restrict__ out)
{
    extern __shared__ float sm[];
    int bid = blockIdx.x, tid = threadIdx.x;
    int lane = tid & 31, warpid = tid >> 5;

    if (bid < NPREP) {
        if (bid >= 13) {
            // ---- nodemeta: 1024 nodes (16 graphs) per block ----
            __shared__ unsigned skmin[256];
            int n = (bid - 13)*1024 + tid;
            float s = __ldg(scalars + (size_t)n * DEG);     // self-loop slot 0
            int4 ns = *(const int4*)(node_states + (size_t)n*4);
            int st = ns.x + 2*ns.y + 4*ns.z + 8*ns.w;
            unsigned key = fkey(s);
            if (tid < 256) skmin[tid] = 0xFFFFFFFFu;
            __syncthreads();
            int slot = ((tid >> 6) << 4) + st;              // 16 graphs x 16 states
            atomicMin(&skmin[slot], key);
            __syncthreads();
            g_row[n]   = 2*st + ((key <= skmin[slot]) ? 1 : 0);
            g_nscal[n] = s;
            __threadfence();
            __syncthreads();
            if (tid == 0) atomicAdd(&g_arrive, 1);
            return;
        }
        // ---- GEMM prep: one 16-row (or 4-row) slice per block ----
        float* sw   = sm;                   // 16384 staged weights
        float* sxp  = sm + 16384;           // 2080  x rows (q-plane layout)
        float* sbuf = sm + 16384 + 2080;    // 2080  row buffer / mid values

        const float* xsrc; const float* wsrc; float* outp = 0;
        int wstride = H, woff = 0, rbase = 0, R = 16, mode;
        // modes: 0 plain, 1 plain-transposed, 2 LN->rowmajor(Q), 3 LN->transposed(K), 4 thr, 5 chained
        switch (bid) {
            case 0:  xsrc=emb_virtual;  wsrc=w_q;   mode=2; outp=g_Qtab;  rbase=0;  break;
            case 1:  xsrc=emb_virtual;  wsrc=w_q;   mode=2; outp=g_Qtab;  rbase=16; break;
            case 2:  xsrc=emb_virtual;  wsrc=w_k;   mode=3; outp=g_KtabT; rbase=0;  break;
            case 3:  xsrc=emb_virtual;  wsrc=w_k;   mode=3; outp=g_KtabT; rbase=16; break;
            case 4:  xsrc=emb_reciever; wsrc=w_ek;  mode=1; outp=g_RtabT; rbase=0;  break;
            case 5:  xsrc=emb_reciever; wsrc=w_ek;  mode=1; outp=g_RtabT; rbase=16; break;
            case 6:  xsrc=emb_virtual;  wsrc=w_v;   mode=0; outp=g_Vtab;  rbase=0;  break;
            case 7:  xsrc=emb_virtual;  wsrc=w_v;   mode=0; outp=g_Vtab;  rbase=16; break;
            case 8:  xsrc=emb_virtual;  wsrc=tg_w1; mode=4; rbase=0;  break;
            case 9:  xsrc=emb_virtual;  wsrc=tg_w1; mode=4; rbase=16; break;
            case 10: xsrc=emb_edge;   wsrc=w_comb; wstride=3*H; woff=0;   mode=5; outp=g_U1; break;
            case 11: xsrc=emb_edge;   wsrc=w_comb; wstride=3*H; woff=H;   mode=5; outp=g_U2; break;
            default: xsrc=emb_static; wsrc=w_comb; wstride=3*H; woff=2*H; mode=5; outp=g_U3; R=4; break;
        }
        for (int i = tid; i < 16384; i += 1024)
            sw[i] = __ldg(wsrc + (size_t)(i >> 7)*wstride + woff + (i & 127));
        for (int i = tid; i < R*H; i += 1024) {
            int r = i >> 7, t = i & 127;
            sxp[(t >> 4)*XPQ + r*16 + (t & 15)] = __ldg(xsrc + (size_t)(rbase + r)*H + t);
        }
        __syncthreads();

        int q = tid & 7, jg = (tid >> 3) & 63, rg = tid >> 9;
        int j0 = jg*2;
        float wreg[2][16];
        #pragma unroll
        for (int jj = 0; jj < 2; jj++) {
            const float4* wp = (const float4*)(sw + (j0 + jj)*H + q*16);
            #pragma unroll
            for (int t4 = 0; t4 < 4; t4++) {
                float4 v = wp[t4];
                wreg[jj][t4*4]=v.x; wreg[jj][t4*4+1]=v.y; wreg[jj][t4*4+2]=v.z; wreg[jj][t4*4+3]=v.w;
            }
        }
        int rows_sub = R >> 1;
        for (int r0 = 0; r0 < rows_sub; r0++) {
            int r = rg*rows_sub + r0;
            float xf[16];
            const float4* xp = (const float4*)(sxp + q*XPQ + r*16);
            #pragma unroll
            for (int t4 = 0; t4 < 4; t4++) {
                float4 v = xp[t4];
                xf[t4*4]=v.x; xf[t4*4+1]=v.y; xf[t4*4+2]=v.z; xf[t4*4+3]=v.w;
            }
            float a0 = 0.f, a1 = 0.f;
            #pragma unroll
            for (int t = 0; t < 16; t++) { a0 += xf[t]*wreg[0][t]; a1 += xf[t]*wreg[1][t]; }
            a0 += __shfl_xor_sync(FULLM,a0,1); a1 += __shfl_xor_sync(FULLM,a1,1);
            a0 += __shfl_xor_sync(FULLM,a0,2); a1 += __shfl_xor_sync(FULLM,a1,2);
            a0 += __shfl_xor_sync(FULLM,a0,4); a1 += __shfl_xor_sync(FULLM,a1,4);
            if (q == 0) {
                if (mode == 0)      { outp[(rbase+r)*H + j0] = a0; outp[(rbase+r)*H + j0+1] = a1; }
                else if (mode == 1) { outp[j0*32 + rbase + r] = a0; outp[(j0+1)*32 + rbase + r] = a1; }
                else if (mode == 2 || mode == 3) { sbuf[r*H + j0] = a0; sbuf[r*H + j0+1] = a1; }
                else if (mode == 4) {
                    sbuf[r*H + j0]   = fmaxf(a0 + __ldg(tg_b1+j0),   0.f) * __ldg(tg_w2+j0);
                    sbuf[r*H + j0+1] = fmaxf(a1 + __ldg(tg_b1+j0+1), 0.f) * __ldg(tg_w2+j0+1);
                } else {
                    sbuf[(j0 >> 4)*XPQ + r*16 + (j0 & 15)]       = a0;
                    sbuf[((j0+1) >> 4)*XPQ + r*16 + ((j0+1)&15)] = a1;
                }
            }
        }
        __syncthreads();

        if (mode == 2 || mode == 3) {            // LN epilogue: warp per row
            if (warpid < R) {
                const float* gp = (mode == 2) ? ln_q_g : ln_k_g;
                const float* bp = (mode == 2) ? ln_q_b : ln_k_b;
                float4 v = *(const float4*)(sbuf + warpid*H + lane*4);
                float s1 = v.x + v.y + v.z + v.w;
                #pragma unroll
                for (int o = 1; o < 32; o <<= 1) s1 += __shfl_xor_sync(FULLM, s1, o);
                float mu = s1 * (1.f/128.f);
                float4 d = make_float4(v.x-mu, v.y-mu, v.z-mu, v.w-mu);
                float s2 = d.x*d.x + d.y*d.y + d.z*d.z + d.w*d.w;
                #pragma unroll
                for (int o = 1; o < 32; o <<= 1) s2 += __shfl_xor_sync(FULLM, s2, o);
                float rs = rsqrtf(s2 * (1.f/128.f) + 1e-5f);
                float4 gv = *(const float4*)(gp + lane*4);
                float4 bv = *(const float4*)(bp + lane*4);
                float o0 = d.x*rs*gv.x+bv.x, o1 = d.y*rs*gv.y+bv.y;
                float o2 = d.z*rs*gv.z+bv.z, o3 = d.w*rs*gv.w+bv.w;
                int rr = rbase + warpid;
                if (mode == 2) {
                    *(float4*)(outp + rr*H + lane*4) = make_float4(o0,o1,o2,o3);
                } else {
                    outp[(lane*4  )*32 + rr] = o0;
                    outp[(lane*4+1)*32 + rr] = o1;
                    outp[(lane*4+2)*32 + rr] = o2;
                    outp[(lane*4+3)*32 + rr] = o3;
                }
            }
        } else if (mode == 4) {                  // thr epilogue
            if (warpid < R) {
                float4 v = *(const float4*)(sbuf + warpid*H + lane*4);
                float s1 = v.x + v.y + v.z + v.w;
                #pragma unroll
                for (int o = 1; o < 32; o <<= 1) s1 += __shfl_xor_sync(FULLM, s1, o);
                if (lane == 0) g_thr[rbase + warpid] = s1 + __ldg(tg_b2);
            }
        } else if (mode == 5) {                  // chained phase 2: @ w_ev.T
            for (int i = tid; i < 16384; i += 1024) sw[i] = __ldg(w_ev + i);
            __syncthreads();
            #pragma unroll
            for (int jj = 0; jj < 2; jj++) {
                const float4* wp = (const float4*)(sw + (j0 + jj)*H + q*16);
                #pragma unroll
                for (int t4 = 0; t4 < 4; t4++) {
                    float4 v = wp[t4];
                    wreg[jj][t4*4]=v.x; wreg[jj][t4*4+1]=v.y; wreg[jj][t4*4+2]=v.z; wreg[jj][t4*4+3]=v.w;
                }
            }
            for (int r0 = 0; r0 < rows_sub; r0++) {
                int r = rg*rows_sub + r0;
                float xf[16];
                const float4* xp = (const float4*)(sbuf + q*XPQ + r*16);
                #pragma unroll
                for (int t4 = 0; t4 < 4; t4++) {
                    float4 v = xp[t4];
                    xf[t4*4]=v.x; xf[t4*4+1]=v.y; xf[t4*4+2]=v.z; xf[t4*4+3]=v.w;
                }
                float a0 = 0.f, a1 = 0.f;
                #pragma unroll
                for (int t = 0; t < 16; t++) { a0 += xf[t]*wreg[0][t]; a1 += xf[t]*wreg[1][t]; }
                a0 += __shfl_xor_sync(FULLM,a0,1); a1 += __shfl_xor_sync(FULLM,a1,1);
                a0 += __shfl_xor_sync(FULLM,a0,2); a1 += __shfl_xor_sync(FULLM,a1,2);
                a0 += __shfl_xor_sync(FULLM,a0,4); a1 += __shfl_xor_sync(FULLM,a1,4);
                if (q == 0) { outp[r*H + j0] = a0; outp[r*H + j0+1] = a1; }
            }
        }
        __threadfence();
        __syncthreads();
        if (tid == 0) atomicAdd(&g_arrive, 1);
        return;
    }

    // ================= main worker block: 32 warps, 1 node each =================
    float*    sV    = sm;
    float*    sU1   = sV   + 4096;
    float*    sU2   = sU1  + 2048;
    float*    sU3   = sU2  + 2048;
    float*    sEdge = sU3  + 512;
    float*    sQ    = sEdge+ 2048;
    float*    sKT   = sQ   + 4096;
    float*    sRT   = sKT  + 4096;
    float*    sQK   = sRT  + 4096;
    float*    sQR   = sQK  + 1024;
    float*    sThr  = sQR  + 1024;
    unsigned* sKmin = (unsigned*)(sThr + 32);    // 32 warps * 16
    unsigned* sMeta = sKmin + 512;               // 32 warps * 32

    // ---- pre-barrier: independent staging + per-warp metadata loads ----
    for (int i = tid; i < 2048; i += 1024) sEdge[i] = __ldg(emb_edge + i);

    int n = (bid - NPREP)*32 + warpid;
    int k = lane;
    int e = (n << 5) + k;
    int off = (k == 0) ? 0 : (k == 31 ? (NNODES/2) : ((k & 1) ? ((k+1) >> 1) : -(k >> 1)));
    int src = (n + off) & (NNODES - 1);
    int rk  = (k == 0) ? 0 : (k == 31 ? 31 : ((k & 1) ? k+1 : k-1));
    int re  = (src << 5) + rk;
    int4 ea = *(const int4*)(edge_states + (size_t)e*4);
    int4 eb = *(const int4*)(edge_states + (size_t)re*4);
    float s = __ldg(scalars + e);
    int a = ea.x + 2*ea.y + 4*ea.z + 8*ea.w;
    int b = eb.x + 2*eb.y + 4*eb.z + 8*eb.w;

    // ---- wait for prep ----
    if (tid == 0) { while (atomicAdd(&g_arrive, 0) < NPREP) __nanosleep(64); }
    __syncthreads();
    __threadfence();

    // ---- stage tables ----
    for (int i = tid; i < 4096; i += 1024) {
        sV[i] = g_Vtab[i]; sQ[i] = g_Qtab[i]; sKT[i] = g_KtabT[i]; sRT[i] = g_RtabT[i];
    }
    for (int i = tid; i < 2048; i += 1024) { sU1[i] = g_U1[i]; sU2[i] = g_U2[i]; }
    for (int i = tid; i < 512;  i += 1024) sU3[i] = g_U3[i];
    if (tid < 32) sThr[tid] = g_thr[tid];
    __syncthreads();

    // ---- per-block QK/QR (warp = Q row, lane = K/R row; conflict-free) ----
    {
        float accK = 0.f, accR = 0.f;
        const float* qrow = sQ + warpid*H;
        #pragma unroll 4
        for (int t = 0; t < H; t++) {
            float qv = qrow[t];
            accK += qv * sKT[t*32 + lane];
            accR += qv * sRT[t*32 + lane];
        }
        sQK[warpid*32 + lane] = accK;
        sQR[warpid*32 + lane] = accR;
    }
    __syncthreads();

    // ---- metadata finish ----
    float recv = __shfl_sync(FULLM, s, 0);
    float send = g_nscal[src];
    int   srow = g_row[src];
    int   c    = (s < recv ? 1 : 0) + ((send + s) < recv ? 2 : 0);
    int   st   = srow >> 1;
    unsigned* wk = sKmin + warpid*16;
    unsigned* wm = sMeta + warpid*32;
    if (lane < 16) wk[lane] = 0xFFFFFFFFu;
    __syncwarp();
    unsigned key = fkey(s);
    atomicMin(&wk[st], key);
    __syncwarp();
    int sbrow = (srow & ~1) + ((key <= wk[st]) ? 1 : 0);
    int myrow = g_row[n];
    float logit = (sQK[myrow*32 + srow] + sQR[myrow*32 + sbrow]) * 0.08838834764831845f;
    unsigned selmask = __ballot_sync(FULLM, logit >= sThr[myrow]);
    wm[lane] = (unsigned)srow | ((unsigned)a << 5) | ((unsigned)b << 9) | ((unsigned)c << 13);
    __syncwarp();

    // ---- compute msg: lane = h-chunk [4*lane, 4*lane+4) ----
    float4 msg = make_float4(0.f, 0.f, 0.f, 0.f);
    #pragma unroll 4
    for (int kk = 0; kk < 32; kk++) {
        if (selmask & (1u << kk)) {
            unsigned m = wm[kk];
            int sr = m & 31, aa = (m >> 5) & 15, bb = (m >> 9) & 15, cc = (m >> 13) & 3;
            float4 V4 = *(const float4*)(sV  + sr*H + lane*4);
            float4 u1 = *(const float4*)(sU1 + aa*H + lane*4);
            float4 u2 = *(const float4*)(sU2 + bb*H + lane*4);
            float4 u3 = *(const float4*)(sU3 + cc*H + lane*4);
            msg.x += V4.x + u1.x + u2.x + u3.x;
            msg.y += V4.y + u1.y + u2.y + u3.y;
            msg.z += V4.z + u1.z + u2.z + u3.z;
            msg.w += V4.w + u1.w + u2.w + u3.w;
        }
    }

    // node_out
    {
        float4 ev = __ldg((const float4*)(emb_virtual + (size_t)myrow*H + lane*4));
        __stcs((float4*)(out + (size_t)n*H + lane*4),
               make_float4(ev.x+msg.x, ev.y+msg.y, ev.z+msg.z, ev.w+msg.w));
    }
    // edge_out
    float* eout = out + (size_t)NNODES*H;
    #pragma unroll 4
    for (int kk = 0; kk < 32; kk++) {
        unsigned m = wm[kk];
        int aa = (m >> 5) & 15;
        float4 ed = *(const float4*)(sEdge + aa*H + lane*4);
        __stcs((float4*)(eout + (size_t)((n << 5) + kk)*H + lane*4),
               make_float4(ed.x+msg.x, ed.y+msg.y, ed.z+msg.z, ed.w+msg.w));
    }

    // ---- counter self-reset (last main block) ----
    __syncthreads();
    if (tid == 0) {
        int d = atomicAdd(&g_done, 1);
        if (d == NMAIN - 1) { g_arrive = 0; __threadfence(); g_done = 0; }
    }
}

// ---------------- launcher ----------------
extern "C" void kernel_launch(void* const* d_in, const int* in_sizes, int n_in,
                              void* d_out, int out_size)
{
    int shift = (n_in >= 26) ? 0 : -1;
    const int*   node_states  = (const int*)  d_in[0];
    const int*   edge_states  = (const int*)  d_in[1];
    const float* scalars      = (const float*)d_in[2];
    const float* emb_virtual  = (const float*)d_in[8+shift];
    const float* emb_reciever = (const float*)d_in[9+shift];
    const float* emb_edge     = (const float*)d_in[10+shift];
    const float* emb_static   = (const float*)d_in[11+shift];
    const float* w_q    = (const float*)d_in[12+shift];
    const float* w_k    = (const float*)d_in[13+shift];
    const float* w_v    = (const float*)d_in[14+shift];
    const float* w_ek   = (const float*)d_in[15+shift];
    const float* w_ev   = (const float*)d_in[16+shift];
    const float* w_comb = (const float*)d_in[17+shift];
    const float* ln_q_g = (const float*)d_in[18+shift];
    const float* ln_q_b = (const float*)d_in[19+shift];
    const float* ln_k_g = (const float*)d_in[20+shift];
    const float* ln_k_b = (const float*)d_in[21+shift];
    const float* tg_w1  = (const float*)d_in[22+shift];
    const float* tg_b1  = (const float*)d_in[23+shift];
    const float* tg_w2  = (const float*)d_in[24+shift];
    const float* tg_b2  = (const float*)d_in[25+shift];

    cudaFuncSetAttribute(k_all, cudaFuncAttributeMaxDynamicSharedMemorySize, SMEM_BYTES);

    k_all<<<NGRID, 1024, SMEM_BYTES>>>(
        scalars, node_states, edge_states,
        emb_virtual, emb_reciever, emb_edge, emb_static,
        w_q, w_k, w_v, w_ek, w_ev, w_comb,
        ln_q_g, ln_q_b, ln_k_g, ln_k_b,
        tg_w1, tg_b1, tg_w2, tg_b2,
        (float*)d_out);
}